// round 1
// baseline (speedup 1.0000x reference)
#include <cuda_runtime.h>
#include <cstdint>

#define N_NODES 100000
#define E_EDGES 500000
#define C       128

// ---------------- scratch (device globals; no allocation allowed) ----------------
__device__ float g_R[(size_t)E_EDGES * C];      // 256 MB: R = edge_attr @ W1c + be1
__device__ float g_PQ[(size_t)N_NODES * 256];   // 102 MB: [h@W1a | h@W1b]
__device__ float g_S[(size_t)N_NODES * C];      // 51 MB : segment-sum of relu(...)
__device__ float g_H1[(size_t)N_NODES * C];     // 51 MB : h after step 0
__device__ float g_Bpack[128 * 256];            // packed [W1a|W1b]
__device__ float g_deg[N_NODES];                // degree (for be2 term)
__device__ int   g_idx64;                       // 1 if edge_index is int64

// ---------------- index dtype detection ----------------
__global__ void detect_idx_kernel(const void* idx) {
    // Interpret the first 4096 entries as int64. If the data is really int32,
    // pairs combine into values >= 2^32 (unless the high word is 0, rare),
    // so "all in [0,N)" robustly identifies int64.
    const long long* p = (const long long*)idx;
    __shared__ int bad;
    if (threadIdx.x == 0) bad = 0;
    __syncthreads();
    for (int i = threadIdx.x; i < 4096; i += blockDim.x) {
        long long v = p[i];
        if (v < 0 || v >= N_NODES) bad = 1;
    }
    __syncthreads();
    if (threadIdx.x == 0) g_idx64 = bad ? 0 : 1;
}

__device__ __forceinline__ int get_idx(const void* idx, int e, int which) {
    if (g_idx64) return (int)((const long long*)idx)[(size_t)which * E_EDGES + e];
    return ((const int*)idx)[(size_t)which * E_EDGES + e];
}

// ---------------- small utility kernels ----------------
__global__ void zero_S_kernel() {
    int i = blockIdx.x * blockDim.x + threadIdx.x;
    const int n4 = N_NODES * C / 4;
    if (i < n4) ((float4*)g_S)[i] = make_float4(0.f, 0.f, 0.f, 0.f);
}

__global__ void zero_deg_kernel() {
    int i = blockIdx.x * blockDim.x + threadIdx.x;
    const int n4 = N_NODES / 4;
    if (i < n4) ((float4*)g_deg)[i] = make_float4(0.f, 0.f, 0.f, 0.f);
}

__global__ void calc_deg_kernel(const void* idx) {
    int e = blockIdx.x * blockDim.x + threadIdx.x;
    if (e < E_EDGES) {
        int v = get_idx(idx, e, 1);
        atomicAdd(&g_deg[v], 1.0f);
    }
}

__global__ void pack_b_kernel(const float* __restrict__ We1) {
    int i = blockIdx.x * blockDim.x + threadIdx.x;
    if (i < 128 * 256) {
        int k = i >> 8, c = i & 255;
        float v = (c < 128) ? We1[k * 128 + c] : We1[(128 + k) * 128 + (c - 128)];
        g_Bpack[i] = v;
    }
}

// ---------------- R = edge_attr @ W1c + be1 (one warp per edge, grid-stride) ----------------
__global__ void __launch_bounds__(256) compute_R_kernel(
    const float* __restrict__ ea, const float* __restrict__ We1,
    const float* __restrict__ be1)
{
    __shared__ float w[32][132];   // W1c rows (We1 rows 256..287), padded (528B rows, 16B-aligned)
    __shared__ float b1[128];
    for (int i = threadIdx.x; i < 32 * 128; i += blockDim.x) {
        int k = i >> 7, c = i & 127;
        w[k][c] = We1[(256 + k) * 128 + c];
    }
    for (int i = threadIdx.x; i < 128; i += blockDim.x) b1[i] = be1[i];
    __syncthreads();

    int warp  = (blockIdx.x * blockDim.x + threadIdx.x) >> 5;
    int lane  = threadIdx.x & 31;
    int nwarp = (gridDim.x * blockDim.x) >> 5;
    for (int e = warp; e < E_EDGES; e += nwarp) {
        float a = ea[(size_t)e * 32 + lane];       // coalesced, broadcast via shfl
        int c0 = lane * 4;
        float4 acc = make_float4(b1[c0], b1[c0 + 1], b1[c0 + 2], b1[c0 + 3]);
        #pragma unroll
        for (int k = 0; k < 32; k++) {
            float s = __shfl_sync(0xffffffffu, a, k);
            float4 wv = *(const float4*)&w[k][c0];
            acc.x += s * wv.x; acc.y += s * wv.y;
            acc.z += s * wv.z; acc.w += s * wv.w;
        }
        *(float4*)&g_R[(size_t)e * C + c0] = acc;
    }
}

// ---------------- edge pass: t = relu(P[ei]+Q[ej]+R[e]); S[ej] += t (one warp/edge) ----------
__global__ void __launch_bounds__(256) edge_pass_kernel(const void* idx) {
    int e = (blockIdx.x * blockDim.x + threadIdx.x) >> 5;
    if (e >= E_EDGES) return;
    int lane = threadIdx.x & 31;
    int ei = get_idx(idx, e, 0);
    int ej = get_idx(idx, e, 1);
    int c0 = lane * 4;
    float4 p = *(const float4*)&g_PQ[(size_t)ei * 256 + c0];
    float4 q = *(const float4*)&g_PQ[(size_t)ej * 256 + 128 + c0];
    float4 r = *(const float4*)&g_R[(size_t)e * C + c0];
    float4 t;
    t.x = fmaxf(p.x + q.x + r.x, 0.f);
    t.y = fmaxf(p.y + q.y + r.y, 0.f);
    t.z = fmaxf(p.z + q.z + r.z, 0.f);
    t.w = fmaxf(p.w + q.w + r.w, 0.f);
    float* dst = &g_S[(size_t)ej * C + c0];
    asm volatile("red.global.add.v4.f32 [%0], {%1, %2, %3, %4};"
                 :: "l"(dst), "f"(t.x), "f"(t.y), "f"(t.z), "f"(t.w) : "memory");
}

// ---------------- fp32 tiled GEMM: C[M,ld] = A[M,128] @ B[128,ldb] (+ epilogue) -------------
// Tile 64(M) x 128(N), BK=16, 128 threads, 8x8 register microtile per thread.
#define BM 64
#define BN 128
#define BK 16

__global__ void __launch_bounds__(128) gemm_k128(
    const float* __restrict__ A, const float* __restrict__ B,
    float* __restrict__ Cout, int M, int ldb, int ldc,
    int epi,                               // 0: plain store, 1: += addsrc + deg*b2 (+bias)
    const float* __restrict__ addsrc,
    const float* __restrict__ b2,
    const float* __restrict__ bias)
{
    __shared__ float As[BK][BM];
    __shared__ float Bs[BK][BN];
    int tid = threadIdx.x;
    int tx = tid & 15;    // N direction (16 threads * 8 cols)
    int ty = tid >> 4;    // M direction (8 threads * 8 rows)
    int m0 = blockIdx.x * BM;
    int n0 = blockIdx.y * BN;

    float acc[8][8];
    #pragma unroll
    for (int i = 0; i < 8; i++)
        #pragma unroll
        for (int j = 0; j < 8; j++) acc[i][j] = 0.f;

    for (int k0 = 0; k0 < 128; k0 += BK) {
        // A tile: 64 rows x 16 k -> transposed into As[k][m]
        #pragma unroll
        for (int t = 0; t < 2; t++) {
            int s = tid * 2 + t;            // 0..255 float4 slots
            int row = s >> 2;               // 0..63
            int cseg = s & 3;               // 0..3
            int gr = m0 + row;
            float4 v = make_float4(0.f, 0.f, 0.f, 0.f);
            if (gr < M) v = *(const float4*)&A[(size_t)gr * 128 + k0 + cseg * 4];
            As[cseg * 4 + 0][row] = v.x;
            As[cseg * 4 + 1][row] = v.y;
            As[cseg * 4 + 2][row] = v.z;
            As[cseg * 4 + 3][row] = v.w;
        }
        // B tile: 16 k x 128 n
        #pragma unroll
        for (int t = 0; t < 4; t++) {
            int s = tid + t * 128;          // 0..511 float4 slots
            int kr = s >> 5;                // 0..15
            int c4 = s & 31;
            *(float4*)&Bs[kr][c4 * 4] =
                *(const float4*)&B[(size_t)(k0 + kr) * ldb + n0 + c4 * 4];
        }
        __syncthreads();
        #pragma unroll
        for (int kk = 0; kk < BK; kk++) {
            float a[8], b[8];
            *(float4*)&a[0] = *(float4*)&As[kk][ty * 8];
            *(float4*)&a[4] = *(float4*)&As[kk][ty * 8 + 4];
            *(float4*)&b[0] = *(float4*)&Bs[kk][tx * 8];
            *(float4*)&b[4] = *(float4*)&Bs[kk][tx * 8 + 4];
            #pragma unroll
            for (int i = 0; i < 8; i++)
                #pragma unroll
                for (int j = 0; j < 8; j++)
                    acc[i][j] += a[i] * b[j];
        }
        __syncthreads();
    }

    #pragma unroll
    for (int i = 0; i < 8; i++) {
        int gr = m0 + ty * 8 + i;
        if (gr >= M) continue;
        float dg = epi ? g_deg[gr] : 0.f;
        #pragma unroll
        for (int j = 0; j < 8; j += 4) {
            int gc = n0 + tx * 8 + j;
            float4 v = make_float4(acc[i][j], acc[i][j+1], acc[i][j+2], acc[i][j+3]);
            if (epi) {
                float4 hv = *(const float4*)&addsrc[(size_t)gr * 128 + gc];
                v.x += hv.x + dg * b2[gc + 0];
                v.y += hv.y + dg * b2[gc + 1];
                v.z += hv.z + dg * b2[gc + 2];
                v.w += hv.w + dg * b2[gc + 3];
                if (bias) {
                    v.x += bias[gc + 0]; v.y += bias[gc + 1];
                    v.z += bias[gc + 2]; v.w += bias[gc + 3];
                }
            }
            *(float4*)&Cout[(size_t)gr * ldc + gc] = v;
        }
    }
}

// ---------------- launch ----------------
extern "C" void kernel_launch(void* const* d_in, const int* in_sizes, int n_in,
                              void* d_out, int out_size) {
    const float* x    = (const float*)d_in[0];
    const void*  eidx = d_in[1];
    const float* ea   = (const float*)d_in[2];
    const float* We1  = (const float*)d_in[3];
    const float* be1  = (const float*)d_in[4];
    const float* We2  = (const float*)d_in[5];
    const float* be2  = (const float*)d_in[6];
    const float* bias = (const float*)d_in[7];
    float* out = (float*)d_out;

    float *pR, *pPQ, *pS, *pH1, *pBpack;
    cudaGetSymbolAddress((void**)&pR,     g_R);
    cudaGetSymbolAddress((void**)&pPQ,    g_PQ);
    cudaGetSymbolAddress((void**)&pS,     g_S);
    cudaGetSymbolAddress((void**)&pH1,    g_H1);
    cudaGetSymbolAddress((void**)&pBpack, g_Bpack);

    const int M = N_NODES;
    const int mblocks = (M + BM - 1) / BM;   // 1563

    // one-time prep (inside the timed graph, but reused across both steps)
    detect_idx_kernel<<<1, 256>>>(eidx);
    pack_b_kernel<<<(128 * 256 + 255) / 256, 256>>>(We1);
    zero_deg_kernel<<<(N_NODES / 4 + 255) / 256, 256>>>();
    calc_deg_kernel<<<(E_EDGES + 255) / 256, 256>>>(eidx);
    compute_R_kernel<<<2048, 256>>>(ea, We1, be1);

    const float* h = x;
    for (int step = 0; step < 2; step++) {
        // PQ = h @ [W1a|W1b]
        gemm_k128<<<dim3(mblocks, 2), 128>>>(h, pBpack, pPQ, M, 256, 256,
                                             0, nullptr, nullptr, nullptr);
        zero_S_kernel<<<(N_NODES * C / 4 + 255) / 256, 256>>>();
        edge_pass_kernel<<<(E_EDGES * 32 + 255) / 256, 256>>>(eidx);
        // h_next = h + S @ We2 + deg*be2 (+ bias on last step)
        float* dst = (step == 1) ? out : pH1;
        gemm_k128<<<dim3(mblocks, 1), 128>>>(pS, We2, dst, M, 128, 128,
                                             1, h, be2, (step == 1) ? bias : nullptr);
        h = pH1;
    }
}

// round 3
// speedup vs baseline: 1.0466x; 1.0466x over previous
#include <cuda_runtime.h>
#include <cuda_bf16.h>
#include <cstdint>

#define N_NODES 100000
#define E_EDGES 500000
#define C       128

// ---------------- scratch (device globals; no allocation allowed) ----------------
__device__ float g_R[(size_t)E_EDGES * C];        // R = edge_attr @ W1c + be1
__device__ float g_PQ[(size_t)N_NODES * 256];     // [h@W1a | h@W1b]
__device__ float g_S[(size_t)N_NODES * C];        // segment-sum of relu(...)
__device__ float g_H1[(size_t)N_NODES * C];       // h after step 0
__device__ __nv_bfloat16 g_W1hi[256 * 128];       // [n][k] transposed split weights
__device__ __nv_bfloat16 g_W1lo[256 * 128];
__device__ __nv_bfloat16 g_W2hi[128 * 128];
__device__ __nv_bfloat16 g_W2lo[128 * 128];
__device__ float g_deg[N_NODES];
__device__ int   g_idx64;

// ---------------- index dtype detection ----------------
__global__ void detect_idx_kernel(const void* idx) {
    const long long* p = (const long long*)idx;
    __shared__ int bad;
    if (threadIdx.x == 0) bad = 0;
    __syncthreads();
    for (int i = threadIdx.x; i < 4096; i += blockDim.x) {
        long long v = p[i];
        if (v < 0 || v >= N_NODES) bad = 1;
    }
    __syncthreads();
    if (threadIdx.x == 0) g_idx64 = bad ? 0 : 1;
}

__device__ __forceinline__ int get_idx(const void* idx, int e, int which) {
    if (g_idx64) return (int)((const long long*)idx)[(size_t)which * E_EDGES + e];
    return ((const int*)idx)[(size_t)which * E_EDGES + e];
}

// ---------------- small utility kernels ----------------
__global__ void zero_S_kernel() {
    int i = blockIdx.x * blockDim.x + threadIdx.x;
    const int n4 = N_NODES * C / 4;
    if (i < n4) ((float4*)g_S)[i] = make_float4(0.f, 0.f, 0.f, 0.f);
}

__global__ void zero_deg_kernel() {
    int i = blockIdx.x * blockDim.x + threadIdx.x;
    const int n4 = N_NODES / 4;
    if (i < n4) ((float4*)g_deg)[i] = make_float4(0.f, 0.f, 0.f, 0.f);
}

__global__ void calc_deg_kernel(const void* idx) {
    int e = blockIdx.x * blockDim.x + threadIdx.x;
    if (e < E_EDGES) {
        int v = get_idx(idx, e, 1);
        atomicAdd(&g_deg[v], 1.0f);
    }
}

// pack transposed split-bf16 weights: W1t[n][k], W2t[n][k]
__global__ void pack_w_kernel(const float* __restrict__ We1,
                              const float* __restrict__ We2) {
    int i = blockIdx.x * blockDim.x + threadIdx.x;
    if (i < 256 * 128) {
        int n = i >> 7, k = i & 127;
        float v = (n < 128) ? We1[k * 128 + n] : We1[(128 + k) * 128 + (n - 128)];
        __nv_bfloat16 h = __float2bfloat16_rn(v);
        g_W1hi[i] = h;
        g_W1lo[i] = __float2bfloat16_rn(v - __bfloat162float(h));
    }
    if (i < 128 * 128) {
        int n = i >> 7, k = i & 127;
        float v = We2[k * 128 + n];
        __nv_bfloat16 h = __float2bfloat16_rn(v);
        g_W2hi[i] = h;
        g_W2lo[i] = __float2bfloat16_rn(v - __bfloat162float(h));
    }
}

// ---------------- R = edge_attr @ W1c + be1 (one warp per edge, fp32 exact) ----------------
__global__ void __launch_bounds__(256) compute_R_kernel(
    const float* __restrict__ ea, const float* __restrict__ We1,
    const float* __restrict__ be1)
{
    __shared__ float w[32][132];
    __shared__ float b1[128];
    for (int i = threadIdx.x; i < 32 * 128; i += blockDim.x) {
        int k = i >> 7, c = i & 127;
        w[k][c] = We1[(256 + k) * 128 + c];
    }
    for (int i = threadIdx.x; i < 128; i += blockDim.x) b1[i] = be1[i];
    __syncthreads();

    int warp  = (blockIdx.x * blockDim.x + threadIdx.x) >> 5;
    int lane  = threadIdx.x & 31;
    int nwarp = (gridDim.x * blockDim.x) >> 5;
    for (int e = warp; e < E_EDGES; e += nwarp) {
        float a = ea[(size_t)e * 32 + lane];
        int c0 = lane * 4;
        float4 acc = make_float4(b1[c0], b1[c0 + 1], b1[c0 + 2], b1[c0 + 3]);
        #pragma unroll
        for (int k = 0; k < 32; k++) {
            float s = __shfl_sync(0xffffffffu, a, k);
            float4 wv = *(const float4*)&w[k][c0];
            acc.x += s * wv.x; acc.y += s * wv.y;
            acc.z += s * wv.z; acc.w += s * wv.w;
        }
        *(float4*)&g_R[(size_t)e * C + c0] = acc;
    }
}

// ---------------- edge pass: t = relu(P[ei]+Q[ej]+R[e]); S[ej] += t ----------
__global__ void __launch_bounds__(256) edge_pass_kernel(const void* idx) {
    int e = (blockIdx.x * blockDim.x + threadIdx.x) >> 5;
    if (e >= E_EDGES) return;
    int lane = threadIdx.x & 31;
    int ei = get_idx(idx, e, 0);
    int ej = get_idx(idx, e, 1);
    int c0 = lane * 4;
    float4 p = *(const float4*)&g_PQ[(size_t)ei * 256 + c0];
    float4 q = *(const float4*)&g_PQ[(size_t)ej * 256 + 128 + c0];
    float4 r = *(const float4*)&g_R[(size_t)e * C + c0];
    float4 t;
    t.x = fmaxf(p.x + q.x + r.x, 0.f);
    t.y = fmaxf(p.y + q.y + r.y, 0.f);
    t.z = fmaxf(p.z + q.z + r.z, 0.f);
    t.w = fmaxf(p.w + q.w + r.w, 0.f);
    float* dst = &g_S[(size_t)ej * C + c0];
    asm volatile("red.global.add.v4.f32 [%0], {%1, %2, %3, %4};"
                 :: "l"(dst), "f"(t.x), "f"(t.y), "f"(t.z), "f"(t.w) : "memory");
}

// ============================================================================
// Warp-MMA split-bf16 GEMM: C[M,*] = A[M,128] @ B[128,N] per 128x128 tile.
// A split hi/lo on the fly into SMEM; B pre-split [n][k] in global.
// C = Ahi*Bhi + Ahi*Blo + Alo*Bhi  via mma.sync.m16n8k16.bf16 (sm_80+ path,
// works on generic sm_103 target where tcgen05 is unavailable).
// ============================================================================

#define SM_AHI 0
#define SM_ALO 32768
#define SM_BHI 65536
#define SM_BLO 98304
#define SMEM_MMA 131072

__device__ __forceinline__ uint32_t smem_u32(const void* p) {
    uint32_t a;
    asm("{ .reg .u64 t; cvta.to.shared.u64 t, %1; cvt.u32.u64 %0, t; }"
        : "=r"(a) : "l"(p));
    return a;
}

__device__ __forceinline__ void ldm_x4(uint32_t& r0, uint32_t& r1,
                                       uint32_t& r2, uint32_t& r3, uint32_t addr) {
    asm volatile("ldmatrix.sync.aligned.m8n8.x4.shared.b16 {%0,%1,%2,%3}, [%4];"
                 : "=r"(r0), "=r"(r1), "=r"(r2), "=r"(r3) : "r"(addr));
}

__device__ __forceinline__ void mma16816(float* c, uint32_t a0, uint32_t a1,
                                         uint32_t a2, uint32_t a3,
                                         uint32_t b0, uint32_t b1) {
    asm volatile("mma.sync.aligned.m16n8k16.row.col.f32.bf16.bf16.f32 "
                 "{%0,%1,%2,%3}, {%4,%5,%6,%7}, {%8,%9}, {%0,%1,%2,%3};"
                 : "+f"(c[0]), "+f"(c[1]), "+f"(c[2]), "+f"(c[3])
                 : "r"(a0), "r"(a1), "r"(a2), "r"(a3), "r"(b0), "r"(b1));
}

__device__ __forceinline__ void split2(float a, float b, uint32_t& hi, uint32_t& lo) {
    __nv_bfloat16 ha = __float2bfloat16_rn(a);
    __nv_bfloat16 hb = __float2bfloat16_rn(b);
    __nv_bfloat162 hp = __nv_bfloat162(ha, hb);
    hi = *(uint32_t*)&hp;
    __nv_bfloat16 la = __float2bfloat16_rn(a - __bfloat162float(ha));
    __nv_bfloat16 lb = __float2bfloat16_rn(b - __bfloat162float(hb));
    __nv_bfloat162 lp = __nv_bfloat162(la, lb);
    lo = *(uint32_t*)&lp;
}

// swizzled byte offset for row-major [128][128] bf16 tile with 16B-chunk XOR
__device__ __forceinline__ uint32_t swz(int row, int chunk) {
    return (uint32_t)(row * 256 + ((chunk ^ (row & 7)) << 4));
}

// One CTA: 128(M) x 128(N) tile. epi=0: C=A@B; epi=1: +=addsrc+deg*b2(+bias)
__global__ void __launch_bounds__(256) gemm_mma(
    const float* __restrict__ A,
    const __nv_bfloat16* __restrict__ Bhi, const __nv_bfloat16* __restrict__ Blo,
    float* __restrict__ Cout, int M, int ldc,
    int epi, const float* __restrict__ addsrc,
    const float* __restrict__ b2, const float* __restrict__ bias)
{
    extern __shared__ char smem[];
    uint32_t sb = smem_u32(smem);
    int tid = threadIdx.x;
    int wid = tid >> 5;
    int lid = tid & 31;
    int m0 = blockIdx.x * 128;
    int n0 = blockIdx.y * 128;

    // ---- stage A (fp32 -> split bf16 hi/lo, swizzled) ----
    for (int s = tid; s < 2048; s += 256) {
        int row = s >> 4, ch = s & 15;
        int gr = m0 + row;
        float4 v0 = make_float4(0.f, 0.f, 0.f, 0.f), v1 = v0;
        if (gr < M) {
            v0 = *(const float4*)&A[(size_t)gr * 128 + ch * 8];
            v1 = *(const float4*)&A[(size_t)gr * 128 + ch * 8 + 4];
        }
        uint32_t h[4], l[4];
        split2(v0.x, v0.y, h[0], l[0]);
        split2(v0.z, v0.w, h[1], l[1]);
        split2(v1.x, v1.y, h[2], l[2]);
        split2(v1.z, v1.w, h[3], l[3]);
        uint32_t off = swz(row, ch);
        *(uint4*)(smem + SM_AHI + off) = make_uint4(h[0], h[1], h[2], h[3]);
        *(uint4*)(smem + SM_ALO + off) = make_uint4(l[0], l[1], l[2], l[3]);
    }
    // ---- stage B (pre-split bf16 [n][k], swizzled) ----
    for (int s = tid; s < 2048; s += 256) {
        int row = s >> 4, ch = s & 15;
        size_t src = (size_t)(n0 + row) * 128 + ch * 8;
        uint4 vh = *(const uint4*)&Bhi[src];
        uint4 vl = *(const uint4*)&Blo[src];
        uint32_t off = swz(row, ch);
        *(uint4*)(smem + SM_BHI + off) = vh;
        *(uint4*)(smem + SM_BLO + off) = vl;
    }
    __syncthreads();

    int warp_m = (wid & 3) * 32;
    int warp_n = (wid >> 2) * 64;
    int half = lid >> 3;       // 0..3 (ldmatrix sub-matrix)
    int r8   = lid & 7;

    float acc[2][8][4];
    #pragma unroll
    for (int i = 0; i < 2; i++)
        #pragma unroll
        for (int j = 0; j < 8; j++)
            #pragma unroll
            for (int q = 0; q < 4; q++) acc[i][j][q] = 0.f;

    #pragma unroll
    for (int prod = 0; prod < 3; prod++) {
        uint32_t abase = sb + (prod == 2 ? SM_ALO : SM_AHI);
        uint32_t bbase = sb + (prod == 1 ? SM_BLO : SM_BHI);
        #pragma unroll
        for (int ks = 0; ks < 8; ks++) {
            // A fragments for 2 m-tiles of 16
            uint32_t a[2][4];
            #pragma unroll
            for (int mt = 0; mt < 2; mt++) {
                int row = warp_m + mt * 16 + ((half & 1) << 3) + r8;
                int ch  = 2 * ks + (half >> 1);
                ldm_x4(a[mt][0], a[mt][1], a[mt][2], a[mt][3], abase + swz(row, ch));
            }
            // B fragments, 4 n-tile pairs (each x4 covers two n-tiles of 8)
            #pragma unroll
            for (int np = 0; np < 4; np++) {
                int rowb = warp_n + np * 16 + ((half >> 1) << 3) + r8;
                int chb  = 2 * ks + (half & 1);
                uint32_t b0, b1, b2r, b3;
                ldm_x4(b0, b1, b2r, b3, bbase + swz(rowb, chb));
                #pragma unroll
                for (int mt = 0; mt < 2; mt++) {
                    mma16816(acc[mt][np * 2],     a[mt][0], a[mt][1], a[mt][2], a[mt][3], b0,  b1);
                    mma16816(acc[mt][np * 2 + 1], a[mt][0], a[mt][1], a[mt][2], a[mt][3], b2r, b3);
                }
            }
        }
    }

    // ---- epilogue ----
    int g = lid >> 2, t = lid & 3;
    #pragma unroll
    for (int mt = 0; mt < 2; mt++) {
        #pragma unroll
        for (int rr = 0; rr < 2; rr++) {          // row / row+8
            int row = m0 + warp_m + mt * 16 + rr * 8 + g;
            if (row >= M) continue;
            float dg = epi ? g_deg[row] : 0.f;
            #pragma unroll
            for (int nt = 0; nt < 8; nt++) {
                int gc = n0 + warp_n + nt * 8 + t * 2;
                float v0 = acc[mt][nt][rr * 2 + 0];
                float v1 = acc[mt][nt][rr * 2 + 1];
                if (epi) {
                    const float* as = &addsrc[(size_t)row * 128 + gc];
                    v0 += as[0] + dg * b2[gc + 0];
                    v1 += as[1] + dg * b2[gc + 1];
                    if (bias) { v0 += bias[gc]; v1 += bias[gc + 1]; }
                }
                float2 outp = make_float2(v0, v1);
                *(float2*)&Cout[(size_t)row * ldc + gc] = outp;
            }
        }
    }
}

// ---------------- launch ----------------
extern "C" void kernel_launch(void* const* d_in, const int* in_sizes, int n_in,
                              void* d_out, int out_size) {
    const float* x    = (const float*)d_in[0];
    const void*  eidx = d_in[1];
    const float* ea   = (const float*)d_in[2];
    const float* We1  = (const float*)d_in[3];
    const float* be1  = (const float*)d_in[4];
    const float* We2  = (const float*)d_in[5];
    const float* be2  = (const float*)d_in[6];
    const float* bias = (const float*)d_in[7];
    float* out = (float*)d_out;

    float *pPQ, *pS, *pH1;
    __nv_bfloat16 *pW1hi, *pW1lo, *pW2hi, *pW2lo;
    cudaGetSymbolAddress((void**)&pPQ,   g_PQ);
    cudaGetSymbolAddress((void**)&pS,    g_S);
    cudaGetSymbolAddress((void**)&pH1,   g_H1);
    cudaGetSymbolAddress((void**)&pW1hi, g_W1hi);
    cudaGetSymbolAddress((void**)&pW1lo, g_W1lo);
    cudaGetSymbolAddress((void**)&pW2hi, g_W2hi);
    cudaGetSymbolAddress((void**)&pW2lo, g_W2lo);

    cudaFuncSetAttribute(gemm_mma, cudaFuncAttributeMaxDynamicSharedMemorySize, SMEM_MMA);

    const int M = N_NODES;
    const int mtiles = (M + 127) / 128;   // 782

    // one-time prep
    detect_idx_kernel<<<1, 256>>>(eidx);
    pack_w_kernel<<<(256 * 128 + 255) / 256, 256>>>(We1, We2);
    zero_deg_kernel<<<(N_NODES / 4 + 255) / 256, 256>>>();
    calc_deg_kernel<<<(E_EDGES + 255) / 256, 256>>>(eidx);
    compute_R_kernel<<<2048, 256>>>(ea, We1, be1);

    const float* h = x;
    for (int step = 0; step < 2; step++) {
        // PQ = h @ [W1a|W1b]   (two 128-col N chunks)
        gemm_mma<<<dim3(mtiles, 2), 256, SMEM_MMA>>>(
            h, pW1hi, pW1lo, pPQ, M, 256, 0, nullptr, nullptr, nullptr);
        zero_S_kernel<<<(N_NODES * C / 4 + 255) / 256, 256>>>();
        edge_pass_kernel<<<(E_EDGES * 32 + 255) / 256, 256>>>(eidx);
        // h_next = h + S @ We2 + deg*be2 (+ bias on last step)
        float* dst = (step == 1) ? out : pH1;
        gemm_mma<<<dim3(mtiles, 1), 256, SMEM_MMA>>>(
            pS, pW2hi, pW2lo, dst, M, 128, 1, h, be2, (step == 1) ? bias : nullptr);
        h = pH1;
    }
}

// round 4
// speedup vs baseline: 1.2726x; 1.2159x over previous
#include <cuda_runtime.h>
#include <cuda_bf16.h>
#include <cstdint>

#define N_NODES 100000
#define E_EDGES 500000
#define C       128

// ---------------- scratch (device globals; no allocation allowed) ----------------
__device__ float g_PQ[(size_t)N_NODES * 256];     // [h@W1a | h@W1b]
__device__ float g_S[(size_t)N_NODES * C];        // segment-sum of relu(...)
__device__ float g_H1[(size_t)N_NODES * C];       // h after step 0
__device__ __nv_bfloat16 g_W1hi[256 * 128];       // [n][k] transposed split weights (W1a|W1b)
__device__ __nv_bfloat16 g_W1lo[256 * 128];
__device__ __nv_bfloat16 g_W2hi[128 * 128];
__device__ __nv_bfloat16 g_W2lo[128 * 128];
__device__ __nv_bfloat16 g_W1chi[128 * 32];       // W1c transposed [n][k], split
__device__ __nv_bfloat16 g_W1clo[128 * 32];
__device__ float g_deg[N_NODES];
__device__ int   g_idx64;

// ---------------- index dtype detection ----------------
__global__ void detect_idx_kernel(const void* idx) {
    const long long* p = (const long long*)idx;
    __shared__ int bad;
    if (threadIdx.x == 0) bad = 0;
    __syncthreads();
    for (int i = threadIdx.x; i < 4096; i += blockDim.x) {
        long long v = p[i];
        if (v < 0 || v >= N_NODES) bad = 1;
    }
    __syncthreads();
    if (threadIdx.x == 0) g_idx64 = bad ? 0 : 1;
}

__device__ __forceinline__ int get_idx(const void* idx, int e, int which) {
    if (g_idx64) return (int)((const long long*)idx)[(size_t)which * E_EDGES + e];
    return ((const int*)idx)[(size_t)which * E_EDGES + e];
}

// ---------------- small utility kernels ----------------
__global__ void zero_S_kernel() {
    int i = blockIdx.x * blockDim.x + threadIdx.x;
    const int n4 = N_NODES * C / 4;
    if (i < n4) ((float4*)g_S)[i] = make_float4(0.f, 0.f, 0.f, 0.f);
}

__global__ void zero_deg_kernel() {
    int i = blockIdx.x * blockDim.x + threadIdx.x;
    const int n4 = N_NODES / 4;
    if (i < n4) ((float4*)g_deg)[i] = make_float4(0.f, 0.f, 0.f, 0.f);
}

__global__ void calc_deg_kernel(const void* idx) {
    int e = blockIdx.x * blockDim.x + threadIdx.x;
    if (e < E_EDGES) {
        int v = get_idx(idx, e, 1);
        atomicAdd(&g_deg[v], 1.0f);
    }
}

// pack transposed split-bf16 weights
__global__ void pack_w_kernel(const float* __restrict__ We1,
                              const float* __restrict__ We2) {
    int i = blockIdx.x * blockDim.x + threadIdx.x;
    if (i < 256 * 128) {
        int n = i >> 7, k = i & 127;
        float v = (n < 128) ? We1[k * 128 + n] : We1[(128 + k) * 128 + (n - 128)];
        __nv_bfloat16 h = __float2bfloat16_rn(v);
        g_W1hi[i] = h;
        g_W1lo[i] = __float2bfloat16_rn(v - __bfloat162float(h));
    }
    if (i < 128 * 128) {
        int n = i >> 7, k = i & 127;
        float v = We2[k * 128 + n];
        __nv_bfloat16 h = __float2bfloat16_rn(v);
        g_W2hi[i] = h;
        g_W2lo[i] = __float2bfloat16_rn(v - __bfloat162float(h));
    }
    if (i < 128 * 32) {
        int n = i >> 5, k = i & 31;
        float v = We1[(256 + k) * 128 + n];
        __nv_bfloat16 h = __float2bfloat16_rn(v);
        g_W1chi[i] = h;
        g_W1clo[i] = __float2bfloat16_rn(v - __bfloat162float(h));
    }
}

// ---------------- MMA helpers ----------------
__device__ __forceinline__ uint32_t smem_u32(const void* p) {
    uint32_t a;
    asm("{ .reg .u64 t; cvta.to.shared.u64 t, %1; cvt.u32.u64 %0, t; }"
        : "=r"(a) : "l"(p));
    return a;
}

__device__ __forceinline__ void ldm_x4(uint32_t& r0, uint32_t& r1,
                                       uint32_t& r2, uint32_t& r3, uint32_t addr) {
    asm volatile("ldmatrix.sync.aligned.m8n8.x4.shared.b16 {%0,%1,%2,%3}, [%4];"
                 : "=r"(r0), "=r"(r1), "=r"(r2), "=r"(r3) : "r"(addr));
}

__device__ __forceinline__ void mma16816(float* c, uint32_t a0, uint32_t a1,
                                         uint32_t a2, uint32_t a3,
                                         uint32_t b0, uint32_t b1) {
    asm volatile("mma.sync.aligned.m16n8k16.row.col.f32.bf16.bf16.f32 "
                 "{%0,%1,%2,%3}, {%4,%5,%6,%7}, {%8,%9}, {%0,%1,%2,%3};"
                 : "+f"(c[0]), "+f"(c[1]), "+f"(c[2]), "+f"(c[3])
                 : "r"(a0), "r"(a1), "r"(a2), "r"(a3), "r"(b0), "r"(b1));
}

__device__ __forceinline__ void split2(float a, float b, uint32_t& hi, uint32_t& lo) {
    __nv_bfloat16 ha = __float2bfloat16_rn(a);
    __nv_bfloat16 hb = __float2bfloat16_rn(b);
    __nv_bfloat162 hp = __nv_bfloat162(ha, hb);
    hi = *(uint32_t*)&hp;
    __nv_bfloat16 la = __float2bfloat16_rn(a - __bfloat162float(ha));
    __nv_bfloat16 lb = __float2bfloat16_rn(b - __bfloat162float(hb));
    __nv_bfloat162 lp = __nv_bfloat162(la, lb);
    lo = *(uint32_t*)&lp;
}

// swizzled byte offset, 256B rows ([128][128] bf16): 16 chunks of 16B
__device__ __forceinline__ uint32_t swz(int row, int chunk) {
    return (uint32_t)(row * 256 + ((chunk ^ (row & 7)) << 4));
}
// swizzled byte offset, 64B rows ([128][32] bf16): 4 chunks of 16B
__device__ __forceinline__ uint32_t swzA(int row, int chunk) {
    return (uint32_t)(row * 64 + ((chunk ^ ((row >> 1) & 3)) << 4));
}

// ============================================================================
// Fused edge kernel: per CTA of 128 edges,
//   R = ea_tile @ W1c (split-bf16 MMA, in registers)
//   t = relu(P[ei] + Q[ej] + R + be1);  S[ej] += t
// ============================================================================
#define EBLK 128

__global__ void __launch_bounds__(256) edge_fused_kernel(
    const void* __restrict__ idx, const float* __restrict__ ea,
    const float* __restrict__ be1)
{
    __shared__ __align__(16) char sAhi[EBLK * 64];   // ea hi [128][32]bf16
    __shared__ __align__(16) char sAlo[EBLK * 64];
    __shared__ __align__(16) char sBhi[128 * 64];    // W1c_t hi [128n][32k]
    __shared__ __align__(16) char sBlo[128 * 64];
    __shared__ int   s_ei[EBLK];
    __shared__ int   s_ej[EBLK];
    __shared__ float s_b1[128];

    int tid = threadIdx.x;
    int wid = tid >> 5;
    int lid = tid & 31;
    int e0 = blockIdx.x * EBLK;

    // stage ea tile -> split bf16
    for (int s = tid; s < EBLK * 8; s += 256) {          // 1024 float4 slots
        int row = s >> 3, f4 = s & 7;
        int e = e0 + row;
        float4 v = make_float4(0.f, 0.f, 0.f, 0.f);
        if (e < E_EDGES) v = *(const float4*)&ea[(size_t)e * 32 + f4 * 4];
        uint32_t h0, l0, h1, l1;
        split2(v.x, v.y, h0, l0);
        split2(v.z, v.w, h1, l1);
        uint32_t off = swzA(row, f4 >> 1) + (f4 & 1) * 8;
        *(uint2*)(sAhi + off) = make_uint2(h0, h1);
        *(uint2*)(sAlo + off) = make_uint2(l0, l1);
    }
    // stage W1c_t (pre-split)
    for (int s = tid; s < 512; s += 256) {               // 512 16B chunks
        int row = s >> 2, ch = s & 3;
        uint4 vh = *(const uint4*)&g_W1chi[row * 32 + ch * 8];
        uint4 vl = *(const uint4*)&g_W1clo[row * 32 + ch * 8];
        uint32_t off = swzA(row, ch);
        *(uint4*)(sBhi + off) = vh;
        *(uint4*)(sBlo + off) = vl;
    }
    // stage indices + bias
    if (tid < 128) {
        int e = e0 + tid;
        s_ei[tid] = (e < E_EDGES) ? get_idx(idx, e, 0) : 0;
        s_b1[tid] = be1[tid];
    } else {
        int e = e0 + tid - 128;
        s_ej[tid - 128] = (e < E_EDGES) ? get_idx(idx, e, 1) : 0;
    }
    __syncthreads();

    int warp_m = (wid & 3) * 32;
    int warp_n = (wid >> 2) * 64;
    int half = lid >> 3;
    int r8 = lid & 7;

    float acc[2][8][4];
    #pragma unroll
    for (int i = 0; i < 2; i++)
        #pragma unroll
        for (int j = 0; j < 8; j++)
            #pragma unroll
            for (int q = 0; q < 4; q++) acc[i][j][q] = 0.f;

    uint32_t abases[3] = { smem_u32(sAhi), smem_u32(sAhi), smem_u32(sAlo) };
    uint32_t bbases[3] = { smem_u32(sBhi), smem_u32(sBlo), smem_u32(sBhi) };
    #pragma unroll
    for (int prod = 0; prod < 3; prod++) {
        uint32_t abase = abases[prod];
        uint32_t bbase = bbases[prod];
        #pragma unroll
        for (int ks = 0; ks < 2; ks++) {
            uint32_t a[2][4];
            #pragma unroll
            for (int mt = 0; mt < 2; mt++) {
                int row = warp_m + mt * 16 + ((half & 1) << 3) + r8;
                int ch = 2 * ks + (half >> 1);
                ldm_x4(a[mt][0], a[mt][1], a[mt][2], a[mt][3], abase + swzA(row, ch));
            }
            #pragma unroll
            for (int np = 0; np < 4; np++) {
                int rowb = warp_n + np * 16 + ((half >> 1) << 3) + r8;
                int chb = 2 * ks + (half & 1);
                uint32_t b0, b1, b2r, b3;
                ldm_x4(b0, b1, b2r, b3, bbase + swzA(rowb, chb));
                #pragma unroll
                for (int mt = 0; mt < 2; mt++) {
                    mma16816(acc[mt][np * 2],     a[mt][0], a[mt][1], a[mt][2], a[mt][3], b0,  b1);
                    mma16816(acc[mt][np * 2 + 1], a[mt][0], a[mt][1], a[mt][2], a[mt][3], b2r, b3);
                }
            }
        }
    }

    // epilogue: gather P/Q, relu, scatter-add to S
    int g = lid >> 2, t = lid & 3;
    #pragma unroll
    for (int mt = 0; mt < 2; mt++) {
        #pragma unroll
        for (int rr = 0; rr < 2; rr++) {
            int erow = warp_m + mt * 16 + rr * 8 + g;
            int e = e0 + erow;
            if (e >= E_EDGES) continue;
            int ei = s_ei[erow];
            int ej = s_ej[erow];
            const float* prow = &g_PQ[(size_t)ei * 256];
            const float* qrow = &g_PQ[(size_t)ej * 256 + 128];
            float* srow = &g_S[(size_t)ej * 128];
            #pragma unroll
            for (int nt = 0; nt < 8; nt++) {
                int gc = warp_n + nt * 8 + t * 2;
                float2 p = *(const float2*)(prow + gc);
                float2 q = *(const float2*)(qrow + gc);
                float t0 = fmaxf(p.x + q.x + acc[mt][nt][rr * 2 + 0] + s_b1[gc], 0.f);
                float t1 = fmaxf(p.y + q.y + acc[mt][nt][rr * 2 + 1] + s_b1[gc + 1], 0.f);
                asm volatile("red.global.add.v2.f32 [%0], {%1, %2};"
                             :: "l"(srow + gc), "f"(t0), "f"(t1) : "memory");
            }
        }
    }
}

// ============================================================================
// Warp-MMA split-bf16 GEMM (512 threads, 16 warps, warp tile 16x64)
// ============================================================================
#define SM_AHI 0
#define SM_ALO 32768
#define SM_BHI 65536
#define SM_BLO 98304
#define SMEM_MMA 131072

__global__ void __launch_bounds__(512) gemm_mma(
    const float* __restrict__ A,
    const __nv_bfloat16* __restrict__ Bhi, const __nv_bfloat16* __restrict__ Blo,
    float* __restrict__ Cout, int M, int ldc,
    int epi, const float* __restrict__ addsrc,
    const float* __restrict__ b2, const float* __restrict__ bias)
{
    extern __shared__ char smem[];
    uint32_t sb = smem_u32(smem);
    int tid = threadIdx.x;
    int wid = tid >> 5;
    int lid = tid & 31;
    int m0 = blockIdx.x * 128;
    int n0 = blockIdx.y * 128;

    // stage A (fp32 -> split bf16 hi/lo, swizzled)
    for (int s = tid; s < 2048; s += 512) {
        int row = s >> 4, ch = s & 15;
        int gr = m0 + row;
        float4 v0 = make_float4(0.f, 0.f, 0.f, 0.f), v1 = v0;
        if (gr < M) {
            v0 = *(const float4*)&A[(size_t)gr * 128 + ch * 8];
            v1 = *(const float4*)&A[(size_t)gr * 128 + ch * 8 + 4];
        }
        uint32_t h[4], l[4];
        split2(v0.x, v0.y, h[0], l[0]);
        split2(v0.z, v0.w, h[1], l[1]);
        split2(v1.x, v1.y, h[2], l[2]);
        split2(v1.z, v1.w, h[3], l[3]);
        uint32_t off = swz(row, ch);
        *(uint4*)(smem + SM_AHI + off) = make_uint4(h[0], h[1], h[2], h[3]);
        *(uint4*)(smem + SM_ALO + off) = make_uint4(l[0], l[1], l[2], l[3]);
    }
    // stage B (pre-split [n][k], swizzled)
    for (int s = tid; s < 2048; s += 512) {
        int row = s >> 4, ch = s & 15;
        size_t src = (size_t)(n0 + row) * 128 + ch * 8;
        uint4 vh = *(const uint4*)&Bhi[src];
        uint4 vl = *(const uint4*)&Blo[src];
        uint32_t off = swz(row, ch);
        *(uint4*)(smem + SM_BHI + off) = vh;
        *(uint4*)(smem + SM_BLO + off) = vl;
    }
    __syncthreads();

    int warp_m = (wid & 7) * 16;
    int warp_n = (wid >> 3) * 64;
    int half = lid >> 3;
    int r8 = lid & 7;

    float acc[8][4];
    #pragma unroll
    for (int j = 0; j < 8; j++)
        #pragma unroll
        for (int q = 0; q < 4; q++) acc[j][q] = 0.f;

    #pragma unroll
    for (int prod = 0; prod < 3; prod++) {
        uint32_t abase = sb + (prod == 2 ? SM_ALO : SM_AHI);
        uint32_t bbase = sb + (prod == 1 ? SM_BLO : SM_BHI);
        #pragma unroll
        for (int ks = 0; ks < 8; ks++) {
            uint32_t a0, a1, a2, a3;
            {
                int row = warp_m + ((half & 1) << 3) + r8;
                int ch = 2 * ks + (half >> 1);
                ldm_x4(a0, a1, a2, a3, abase + swz(row, ch));
            }
            #pragma unroll
            for (int np = 0; np < 4; np++) {
                int rowb = warp_n + np * 16 + ((half >> 1) << 3) + r8;
                int chb = 2 * ks + (half & 1);
                uint32_t b0, b1, b2r, b3;
                ldm_x4(b0, b1, b2r, b3, bbase + swz(rowb, chb));
                mma16816(acc[np * 2],     a0, a1, a2, a3, b0,  b1);
                mma16816(acc[np * 2 + 1], a0, a1, a2, a3, b2r, b3);
            }
        }
    }

    // epilogue
    int g = lid >> 2, t = lid & 3;
    #pragma unroll
    for (int rr = 0; rr < 2; rr++) {
        int row = m0 + warp_m + rr * 8 + g;
        if (row >= M) continue;
        float dg = epi ? g_deg[row] : 0.f;
        #pragma unroll
        for (int nt = 0; nt < 8; nt++) {
            int gc = n0 + warp_n + nt * 8 + t * 2;
            float v0 = acc[nt][rr * 2 + 0];
            float v1 = acc[nt][rr * 2 + 1];
            if (epi) {
                const float* as = &addsrc[(size_t)row * 128 + gc];
                v0 += as[0] + dg * b2[gc + 0];
                v1 += as[1] + dg * b2[gc + 1];
                if (bias) { v0 += bias[gc]; v1 += bias[gc + 1]; }
            }
            *(float2*)&Cout[(size_t)row * ldc + gc] = make_float2(v0, v1);
        }
    }
}

// ---------------- launch ----------------
extern "C" void kernel_launch(void* const* d_in, const int* in_sizes, int n_in,
                              void* d_out, int out_size) {
    const float* x    = (const float*)d_in[0];
    const void*  eidx = d_in[1];
    const float* ea   = (const float*)d_in[2];
    const float* We1  = (const float*)d_in[3];
    const float* be1  = (const float*)d_in[4];
    const float* We2  = (const float*)d_in[5];
    const float* be2  = (const float*)d_in[6];
    const float* bias = (const float*)d_in[7];
    float* out = (float*)d_out;

    float *pPQ, *pS, *pH1;
    __nv_bfloat16 *pW1hi, *pW1lo, *pW2hi, *pW2lo;
    cudaGetSymbolAddress((void**)&pPQ,   g_PQ);
    cudaGetSymbolAddress((void**)&pS,    g_S);
    cudaGetSymbolAddress((void**)&pH1,   g_H1);
    cudaGetSymbolAddress((void**)&pW1hi, g_W1hi);
    cudaGetSymbolAddress((void**)&pW1lo, g_W1lo);
    cudaGetSymbolAddress((void**)&pW2hi, g_W2hi);
    cudaGetSymbolAddress((void**)&pW2lo, g_W2lo);

    cudaFuncSetAttribute(gemm_mma, cudaFuncAttributeMaxDynamicSharedMemorySize, SMEM_MMA);

    const int M = N_NODES;
    const int mtiles = (M + 127) / 128;          // 782
    const int eblocks = (E_EDGES + EBLK - 1) / EBLK;  // 3907

    // one-time prep
    detect_idx_kernel<<<1, 256>>>(eidx);
    pack_w_kernel<<<(256 * 128 + 255) / 256, 256>>>(We1, We2);
    zero_deg_kernel<<<(N_NODES / 4 + 255) / 256, 256>>>();
    calc_deg_kernel<<<(E_EDGES + 255) / 256, 256>>>(eidx);

    const float* h = x;
    for (int step = 0; step < 2; step++) {
        gemm_mma<<<dim3(mtiles, 2), 512, SMEM_MMA>>>(
            h, pW1hi, pW1lo, pPQ, M, 256, 0, nullptr, nullptr, nullptr);
        zero_S_kernel<<<(N_NODES * C / 4 + 255) / 256, 256>>>();
        edge_fused_kernel<<<eblocks, 256>>>(eidx, ea, be1);
        float* dst = (step == 1) ? out : pH1;
        gemm_mma<<<dim3(mtiles, 1), 512, SMEM_MMA>>>(
            pS, pW2hi, pW2lo, dst, M, 128, 1, h, be2, (step == 1) ? bias : nullptr);
        h = pH1;
    }
}